// round 7
// baseline (speedup 1.0000x reference)
#include <cuda_runtime.h>
#include <cuda_bf16.h>
#include <cstdint>

#define SL 2048
#define RL 384
#define NCH 16     // s-chunks of 128
#define PSTR 36    // plane row stride in 32-bit words (conflict-free: bank=(4g+c)&31)

// ---------------- device scratch (no runtime allocation allowed) ----------
__device__ __align__(16) float  g_kv[(size_t)RL * SL * 16];   // k|v per (r,s): 50MB
__device__ __align__(16) float  g_pool[NCH * RL * 64];        // partial pools
__device__ __align__(16) float  g_obuf[RL * 64];              // attention output per column
__device__ __align__(16) uint4  g_wG[4 * 8 * 32];             // Wg bf16 frags {bh0,bh1,bl0,bl1}
__device__ __align__(16) uint4  g_wO[4 * 8 * 32];             // Wo frags
__device__ __align__(16) uint4  g_wKV[4 * 2 * 32];            // [Wk|Wv] frags

// ---------------- helpers --------------------------------------------------
__device__ __forceinline__ uint32_t pack2(__nv_bfloat16 a, __nv_bfloat16 b) {
    __nv_bfloat162 t; t.x = a; t.y = b;
    return *reinterpret_cast<uint32_t*>(&t);
}
// split two floats into packed bf16 hi-word and lo-word (x = hi + lo, err ~2^-17)
__device__ __forceinline__ void split2(float x0, float x1, uint32_t& hi, uint32_t& lo) {
    __nv_bfloat16 h0 = __float2bfloat16(x0), h1 = __float2bfloat16(x1);
    float r0 = x0 - __bfloat162float(h0), r1 = x1 - __bfloat162float(h1);
    hi = pack2(h0, h1);
    lo = pack2(__float2bfloat16(r0), __float2bfloat16(r1));
}
__device__ __forceinline__ float bfhalf(uint32_t w, int sh) {
    return __bfloat162float(__ushort_as_bfloat16((unsigned short)(w >> sh)));
}
__device__ __forceinline__ void mma16(float* d, const uint32_t* a, const uint32_t* b) {
    asm volatile(
        "mma.sync.aligned.m16n8k16.row.col.f32.bf16.bf16.f32 "
        "{%0,%1,%2,%3}, {%4,%5,%6,%7}, {%8,%9}, {%0,%1,%2,%3};"
        : "+f"(d[0]), "+f"(d[1]), "+f"(d[2]), "+f"(d[3])
        : "r"(a[0]), "r"(a[1]), "r"(a[2]), "r"(a[3]), "r"(b[0]), "r"(b[1]));
}
__device__ __forceinline__ float sigm(float x) { return 1.f / (1.f + __expf(-x)); }

// ---------------- init: build bf16 hi/lo B fragments (m16n8k16 col-major) --
__global__ void init_kernel(const float* __restrict__ Wg, const float* __restrict__ Wo,
                            const float* __restrict__ Wk, const float* __restrict__ Wv) {
    int tid = blockIdx.x * blockDim.x + threadIdx.x;
    if (tid < 1024) {  // 4 ktiles(k16) x 8 ntiles x 32 lanes for Wg/Wo (64x64)
        int kk = tid >> 8, l = tid & 31;
        int c = l & 3, g = l >> 2;
        int nn = (tid >> 5) & 7;
        int col = nn * 8 + g;
        int k0 = kk * 16 + 2 * c;
        {
            uint32_t h0, l0, h1, l1;
            split2(Wg[k0 * 64 + col],       Wg[(k0 + 1) * 64 + col], h0, l0);
            split2(Wg[(k0 + 8) * 64 + col], Wg[(k0 + 9) * 64 + col], h1, l1);
            g_wG[tid] = make_uint4(h0, h1, l0, l1);
        }
        {
            uint32_t h0, l0, h1, l1;
            split2(Wo[k0 * 64 + col],       Wo[(k0 + 1) * 64 + col], h0, l0);
            split2(Wo[(k0 + 8) * 64 + col], Wo[(k0 + 9) * 64 + col], h1, l1);
            g_wO[tid] = make_uint4(h0, h1, l0, l1);
        }
    }
    if (tid < 256) {  // 4 ktiles x 2 ntiles x 32 lanes for [Wk|Wv] (64x16)
        int kk = tid >> 6, l = tid & 31;
        int c = l & 3, g = l >> 2;
        int nt = (tid >> 5) & 1;
        int col = nt * 8 + g;  // 0..15: first 8 = k, last 8 = v
        const float* W = (col < 8) ? Wk : Wv;
        int cc = col & 7;
        int k0 = kk * 16 + 2 * c;
        uint32_t h0, l0, h1, l1;
        split2(W[k0 * 8 + cc],       W[(k0 + 1) * 8 + cc], h0, l0);
        split2(W[(k0 + 8) * 8 + cc], W[(k0 + 9) * 8 + cc], h1, l1);
        g_wKV[tid] = make_uint4(h0, h1, l0, l1);
    }
}

// ---------------- shared body: load m chunk, LN, split into bf16 planes ----
// plane[0..128*PSTR)       : hi plane (row stride PSTR words, k-pairs packed)
// plane[128*PSTR..2*)      : lo plane
// the same buffer doubles as the fp32 staging area (stride 68 floats)
__device__ __forceinline__ void load_ln_split(const float* __restrict__ mb,
                                              const float* __restrict__ lw,
                                              const float* __restrict__ lb,
                                              uint32_t* plane, int tid) {
    float* stage = reinterpret_cast<float*>(plane);
#pragma unroll
    for (int i = 0; i < 8; i++) {
        int f = tid + i * 256, row = f >> 4, q = f & 15;
        *reinterpret_cast<float4*>(stage + row * 68 + q * 4) =
            *reinterpret_cast<const float4*>(mb + (size_t)row * (RL * 64) + q * 4);
    }
    __syncthreads();
    float v[64];
    bool act = tid < 128;
    if (act) {
#pragma unroll
        for (int q = 0; q < 16; q++) {
            float4 t = *reinterpret_cast<float4*>(stage + tid * 68 + q * 4);
            v[4 * q] = t.x; v[4 * q + 1] = t.y; v[4 * q + 2] = t.z; v[4 * q + 3] = t.w;
        }
        float s = 0.f;
#pragma unroll
        for (int c = 0; c < 64; c++) s += v[c];
        float mu = s * (1.f / 64.f);
        float s2 = 0.f;
#pragma unroll
        for (int c = 0; c < 64; c++) { float d = v[c] - mu; s2 += d * d; }
        float inv = rsqrtf(s2 * (1.f / 64.f) + 1e-5f);
#pragma unroll
        for (int c = 0; c < 64; c++) v[c] = (v[c] - mu) * inv * lw[c] + lb[c];
    }
    __syncthreads();   // all stage reads done before plane writes clobber it
    if (act) {
        uint32_t* hip = plane + tid * PSTR;
        uint32_t* lop = plane + 128 * PSTR + tid * PSTR;
#pragma unroll
        for (int q = 0; q < 32; q++) {
            uint32_t h, lo;
            split2(v[2 * q], v[2 * q + 1], h, lo);
            hip[q] = h; lop[q] = lo;
        }
    }
    __syncthreads();
}

// ---------------- pass A: LN + pool partial + k,v GEMM ---------------------
__global__ __launch_bounds__(256, 3) void passA(const float* __restrict__ m,
                                                const float* __restrict__ lnw,
                                                const float* __restrict__ lnb) {
    __shared__ __align__(16) uint32_t plane[2 * 128 * PSTR];
    __shared__ float lw[64], lb[64];
    int chunk = blockIdx.x, r = blockIdx.y, tid = threadIdx.x;
    if (tid < 64) { lw[tid] = lnw[tid]; lb[tid] = lnb[tid]; }
    const float* mb = m + ((size_t)chunk * 128 * RL + r) * 64;
    load_ln_split(mb, lw, lb, plane, tid);

    // deterministic partial pool (reconstruct x = hi + lo)
    if (tid < 64) {
        int q = tid >> 1, sh = (tid & 1) * 16;
        float s = 0.f;
#pragma unroll 4
        for (int j = 0; j < 128; j++)
            s += bfhalf(plane[j * PSTR + q], sh) + bfhalf(plane[128 * PSTR + j * PSTR + q], sh);
        g_pool[((size_t)chunk * RL + r) * 64 + tid] = s;
    }

    // k,v GEMM: 128x16x64, bf16x3 m16n8k16
    int w = tid >> 5, l = tid & 31, g = l >> 2, c = l & 3;
    int row0 = w * 16 + g;
    const uint32_t* hip = plane;
    const uint32_t* lop = plane + 128 * PSTR;
    float acc[2][4] = {};
#pragma unroll
    for (int kk = 0; kk < 4; kk++) {
        uint32_t ah[4], al[4];
        int b0 = row0 * PSTR + 8 * kk + c, b1 = (row0 + 8) * PSTR + 8 * kk + c;
        ah[0] = hip[b0]; ah[1] = hip[b1]; ah[2] = hip[b0 + 4]; ah[3] = hip[b1 + 4];
        al[0] = lop[b0]; al[1] = lop[b1]; al[2] = lop[b0 + 4]; al[3] = lop[b1 + 4];
#pragma unroll
        for (int nn = 0; nn < 2; nn++) {
            uint4 bw = g_wKV[(kk * 2 + nn) * 32 + l];
            uint32_t bh[2] = {bw.x, bw.y}, bl[2] = {bw.z, bw.w};
            mma16(acc[nn], ah, bh);
            mma16(acc[nn], al, bh);
            mma16(acc[nn], ah, bl);
        }
    }
    float* kp = g_kv + ((size_t)r * SL + (size_t)chunk * 128 + w * 16) * 16;
#pragma unroll
    for (int nn = 0; nn < 2; nn++) {
        int col = nn * 8 + 2 * c;
        *reinterpret_cast<float2*>(&kp[g * 16 + col])       = make_float2(acc[nn][0], acc[nn][1]);
        *reinterpret_cast<float2*>(&kp[(g + 8) * 16 + col]) = make_float2(acc[nn][2], acc[nn][3]);
    }
}

// ---------------- pass B: q, softmax over s, o -----------------------------
__global__ __launch_bounds__(256) void passB(const float* __restrict__ Wq) {
    int r = blockIdx.x, tid = threadIdx.x;
    __shared__ float pool[64], qs[64], mh[8];
    __shared__ float red[8 * 72];
    if (tid < 64) {
        float s = 0.f;
#pragma unroll
        for (int ch = 0; ch < NCH; ch++) s += g_pool[((size_t)ch * RL + r) * 64 + tid];
        pool[tid] = s / (2048.f + 1e-10f);
    }
    __syncthreads();
    if (tid < 64) {
        float a = 0.f;
        for (int c = 0; c < 64; c++) a += pool[c] * Wq[c * 64 + tid];
        qs[tid] = a * 0.35355339059327373f;  // 8^-0.5
    }
    __syncthreads();

    const float* kvr = g_kv + (size_t)r * SL * 16;
    float lmx[8];
#pragma unroll
    for (int h = 0; h < 8; h++) lmx[h] = -1e30f;
    for (int i = 0; i < 8; i++) {
        int s = tid + i * 256;
        float4 k0 = *reinterpret_cast<const float4*>(kvr + (size_t)s * 16);
        float4 k1 = *reinterpret_cast<const float4*>(kvr + (size_t)s * 16 + 4);
#pragma unroll
        for (int h = 0; h < 8; h++) {
            const float* q = &qs[h * 8];
            float lg = q[0] * k0.x + q[1] * k0.y + q[2] * k0.z + q[3] * k0.w +
                       q[4] * k1.x + q[5] * k1.y + q[6] * k1.z + q[7] * k1.w;
            lmx[h] = fmaxf(lmx[h], lg);
        }
    }
#pragma unroll
    for (int o = 16; o; o >>= 1)
#pragma unroll
        for (int h = 0; h < 8; h++) lmx[h] = fmaxf(lmx[h], __shfl_xor_sync(~0u, lmx[h], o));
    int w = tid >> 5, ln = tid & 31;
    if (ln == 0)
        for (int h = 0; h < 8; h++) red[w * 8 + h] = lmx[h];
    __syncthreads();
    if (tid < 8) {
        float mm = -1e30f;
        for (int ww = 0; ww < 8; ww++) mm = fmaxf(mm, red[ww * 8 + tid]);
        mh[tid] = mm;
    }
    __syncthreads();

    float acc[64], sums[8];
#pragma unroll
    for (int j = 0; j < 64; j++) acc[j] = 0.f;
#pragma unroll
    for (int h = 0; h < 8; h++) sums[h] = 0.f;
    for (int i = 0; i < 8; i++) {
        int s = tid + i * 256;
        float4 k0 = *reinterpret_cast<const float4*>(kvr + (size_t)s * 16);
        float4 k1 = *reinterpret_cast<const float4*>(kvr + (size_t)s * 16 + 4);
        float4 v0 = *reinterpret_cast<const float4*>(kvr + (size_t)s * 16 + 8);
        float4 v1 = *reinterpret_cast<const float4*>(kvr + (size_t)s * 16 + 12);
        float vv[8] = {v0.x, v0.y, v0.z, v0.w, v1.x, v1.y, v1.z, v1.w};
#pragma unroll
        for (int h = 0; h < 8; h++) {
            const float* q = &qs[h * 8];
            float lg = q[0] * k0.x + q[1] * k0.y + q[2] * k0.z + q[3] * k0.w +
                       q[4] * k1.x + q[5] * k1.y + q[6] * k1.z + q[7] * k1.w;
            float p = __expf(lg - mh[h]);
            sums[h] += p;
#pragma unroll
            for (int c2 = 0; c2 < 8; c2++) acc[h * 8 + c2] += p * vv[c2];
        }
    }
#pragma unroll
    for (int o = 16; o; o >>= 1) {
#pragma unroll
        for (int h = 0; h < 8; h++) sums[h] += __shfl_xor_sync(~0u, sums[h], o);
#pragma unroll
        for (int j = 0; j < 64; j++) acc[j] += __shfl_xor_sync(~0u, acc[j], o);
    }
    __syncthreads();
    if (ln == 0) {
        for (int h = 0; h < 8; h++) red[w * 72 + h] = sums[h];
        for (int j = 0; j < 64; j++) red[w * 72 + 8 + j] = acc[j];
    }
    __syncthreads();
    if (tid < 64) {
        float a = 0.f, ss = 0.f;
        for (int ww = 0; ww < 8; ww++) a += red[ww * 72 + 8 + tid];
        for (int ww = 0; ww < 8; ww++) ss += red[ww * 72 + (tid >> 3)];
        g_obuf[r * 64 + tid] = a / ss;
    }
}

// ---------------- pass C: LN + GEMM1(sig*o) + GEMM2 + store ----------------
__global__ __launch_bounds__(256, 3) void passC(const float* __restrict__ m,
                                                const float* __restrict__ lnw,
                                                const float* __restrict__ lnb,
                                                const float* __restrict__ bg,
                                                const float* __restrict__ bo,
                                                float* __restrict__ out) {
    __shared__ __align__(16) uint32_t plane[2 * 128 * PSTR];
    __shared__ float lw[64], lb[64], sg[64], sb[64], so[64];
    int chunk = blockIdx.x, r = blockIdx.y, tid = threadIdx.x;
    if (tid < 64) {
        lw[tid] = lnw[tid]; lb[tid] = lnb[tid];
        sg[tid] = bg[tid];  sb[tid] = bo[tid];
        so[tid] = g_obuf[r * 64 + tid];
    }
    const float* mb = m + ((size_t)chunk * 128 * RL + r) * 64;
    load_ln_split(mb, lw, lb, plane, tid);

    int w = tid >> 5, l = tid & 31, g = l >> 2, c = l & 3;
    int row0 = w * 16 + g;
    uint32_t* hip = plane;
    uint32_t* lop = plane + 128 * PSTR;

    // GEMM1: x(128x64) @ Wg(64x64), bf16x3
    float acc[8][4] = {};
#pragma unroll
    for (int kk = 0; kk < 4; kk++) {
        uint32_t ah[4], al[4];
        int b0 = row0 * PSTR + 8 * kk + c, b1 = (row0 + 8) * PSTR + 8 * kk + c;
        ah[0] = hip[b0]; ah[1] = hip[b1]; ah[2] = hip[b0 + 4]; ah[3] = hip[b1 + 4];
        al[0] = lop[b0]; al[1] = lop[b1]; al[2] = lop[b0 + 4]; al[3] = lop[b1 + 4];
#pragma unroll
        for (int nn = 0; nn < 8; nn++) {
            uint4 bw = g_wG[(kk * 8 + nn) * 32 + l];
            uint32_t bh[2] = {bw.x, bw.y}, bl[2] = {bw.z, bw.w};
            mma16(acc[nn], ah, bh);
            mma16(acc[nn], al, bh);
            mma16(acc[nn], ah, bl);
        }
    }
    __syncwarp();  // each warp only touches its own 16 rows; cross-lane within warp

    // epilogue: z = sigmoid(acc + bg) * o  -> split back into planes
#pragma unroll
    for (int nn = 0; nn < 8; nn++) {
        int col = nn * 8 + 2 * c;
        float z0 = sigm(acc[nn][0] + sg[col])     * so[col];
        float z1 = sigm(acc[nn][1] + sg[col + 1]) * so[col + 1];
        float z2 = sigm(acc[nn][2] + sg[col])     * so[col];
        float z3 = sigm(acc[nn][3] + sg[col + 1]) * so[col + 1];
        uint32_t h, lo;
        split2(z0, z1, h, lo);
        hip[row0 * PSTR + 4 * nn + c] = h; lop[row0 * PSTR + 4 * nn + c] = lo;
        split2(z2, z3, h, lo);
        hip[(row0 + 8) * PSTR + 4 * nn + c] = h; lop[(row0 + 8) * PSTR + 4 * nn + c] = lo;
        acc[nn][0] = acc[nn][1] = acc[nn][2] = acc[nn][3] = 0.f;
    }
    __syncwarp();

    // GEMM2: z(128x64) @ Wo(64x64), bf16x3
#pragma unroll
    for (int kk = 0; kk < 4; kk++) {
        uint32_t ah[4], al[4];
        int b0 = row0 * PSTR + 8 * kk + c, b1 = (row0 + 8) * PSTR + 8 * kk + c;
        ah[0] = hip[b0]; ah[1] = hip[b1]; ah[2] = hip[b0 + 4]; ah[3] = hip[b1 + 4];
        al[0] = lop[b0]; al[1] = lop[b1]; al[2] = lop[b0 + 4]; al[3] = lop[b1 + 4];
#pragma unroll
        for (int nn = 0; nn < 8; nn++) {
            uint4 bw = g_wO[(kk * 8 + nn) * 32 + l];
            uint32_t bh[2] = {bw.x, bw.y}, bl[2] = {bw.z, bw.w};
            mma16(acc[nn], ah, bh);
            mma16(acc[nn], al, bh);
            mma16(acc[nn], ah, bl);
        }
    }

    // store: out[s][r][c] with bias bo
    float* ob = out + ((size_t)chunk * 128 * RL + r) * 64;
#pragma unroll
    for (int nn = 0; nn < 8; nn++) {
        int col = nn * 8 + 2 * c;
        *reinterpret_cast<float2*>(&ob[(size_t)row0 * (RL * 64) + col]) =
            make_float2(acc[nn][0] + sb[col], acc[nn][1] + sb[col + 1]);
        *reinterpret_cast<float2*>(&ob[(size_t)(row0 + 8) * (RL * 64) + col]) =
            make_float2(acc[nn][2] + sb[col], acc[nn][3] + sb[col + 1]);
    }
}

// ---------------- launch ----------------------------------------------------
extern "C" void kernel_launch(void* const* d_in, const int* in_sizes, int n_in,
                              void* d_out, int out_size) {
    const float* m   = (const float*)d_in[0];
    const float* lnw = (const float*)d_in[1];
    const float* lnb = (const float*)d_in[2];
    const float* Wq  = (const float*)d_in[3];
    const float* Wk  = (const float*)d_in[4];
    const float* Wv  = (const float*)d_in[5];
    const float* Wg  = (const float*)d_in[6];
    const float* bg  = (const float*)d_in[7];
    const float* Wo  = (const float*)d_in[8];
    const float* bo  = (const float*)d_in[9];
    float* out = (float*)d_out;

    init_kernel<<<4, 256>>>(Wg, Wo, Wk, Wv);
    dim3 gA(NCH, RL);
    passA<<<gA, 256>>>(m, lnw, lnb);
    passB<<<RL, 256>>>(Wq);
    passC<<<gA, 256>>>(m, lnw, lnb, bg, bo, out);
}

// round 8
// speedup vs baseline: 1.0090x; 1.0090x over previous
#include <cuda_runtime.h>
#include <cuda_bf16.h>
#include <cstdint>

#define SL 2048
#define RL 384
#define NCH 16     // s-chunks of 128
#define PSTR 36    // plane row stride in 32-bit words (conflict-free: bank=(4g+c)&31)

// ---------------- device scratch (no runtime allocation allowed) ----------
__device__ __align__(16) float  g_kv[(size_t)RL * SL * 16];   // k|v per (r,s): 50MB
__device__ __align__(16) float  g_pool[NCH * RL * 64];        // partial pools
__device__ __align__(16) float  g_obuf[RL * 64];              // attention output per column
__device__ __align__(16) uint4  g_wG[4 * 8 * 32];             // Wg bf16 frags {bh0,bh1,bl0,bl1}
__device__ __align__(16) uint4  g_wO[4 * 8 * 32];             // Wo frags
__device__ __align__(16) uint4  g_wKV[4 * 2 * 32];            // [Wk|Wv] frags

// ---------------- helpers --------------------------------------------------
__device__ __forceinline__ uint32_t pack2(__nv_bfloat16 a, __nv_bfloat16 b) {
    __nv_bfloat162 t; t.x = a; t.y = b;
    return *reinterpret_cast<uint32_t*>(&t);
}
// split two floats into packed bf16 hi-word and lo-word (x = hi + lo, err ~2^-17)
__device__ __forceinline__ void split2(float x0, float x1, uint32_t& hi, uint32_t& lo) {
    __nv_bfloat16 h0 = __float2bfloat16(x0), h1 = __float2bfloat16(x1);
    float r0 = x0 - __bfloat162float(h0), r1 = x1 - __bfloat162float(h1);
    hi = pack2(h0, h1);
    lo = pack2(__float2bfloat16(r0), __float2bfloat16(r1));
}
__device__ __forceinline__ float bfhalf(uint32_t w, int sh) {
    return __bfloat162float(__ushort_as_bfloat16((unsigned short)(w >> sh)));
}
__device__ __forceinline__ void mma16(float* d, const uint32_t* a, const uint32_t* b) {
    asm volatile(
        "mma.sync.aligned.m16n8k16.row.col.f32.bf16.bf16.f32 "
        "{%0,%1,%2,%3}, {%4,%5,%6,%7}, {%8,%9}, {%0,%1,%2,%3};"
        : "+f"(d[0]), "+f"(d[1]), "+f"(d[2]), "+f"(d[3])
        : "r"(a[0]), "r"(a[1]), "r"(a[2]), "r"(a[3]), "r"(b[0]), "r"(b[1]));
}
__device__ __forceinline__ float sigm(float x) { return 1.f / (1.f + __expf(-x)); }

// ---------------- init: build bf16 hi/lo B fragments (m16n8k16 col-major) --
__global__ void init_kernel(const float* __restrict__ Wg, const float* __restrict__ Wo,
                            const float* __restrict__ Wk, const float* __restrict__ Wv) {
    int tid = blockIdx.x * blockDim.x + threadIdx.x;
    if (tid < 1024) {  // 4 ktiles(k16) x 8 ntiles x 32 lanes for Wg/Wo (64x64)
        int kk = tid >> 8, l = tid & 31;
        int c = l & 3, g = l >> 2;
        int nn = (tid >> 5) & 7;
        int col = nn * 8 + g;
        int k0 = kk * 16 + 2 * c;
        {
            uint32_t h0, l0, h1, l1;
            split2(Wg[k0 * 64 + col],       Wg[(k0 + 1) * 64 + col], h0, l0);
            split2(Wg[(k0 + 8) * 64 + col], Wg[(k0 + 9) * 64 + col], h1, l1);
            g_wG[tid] = make_uint4(h0, h1, l0, l1);
        }
        {
            uint32_t h0, l0, h1, l1;
            split2(Wo[k0 * 64 + col],       Wo[(k0 + 1) * 64 + col], h0, l0);
            split2(Wo[(k0 + 8) * 64 + col], Wo[(k0 + 9) * 64 + col], h1, l1);
            g_wO[tid] = make_uint4(h0, h1, l0, l1);
        }
    }
    if (tid < 256) {  // 4 ktiles x 2 ntiles x 32 lanes for [Wk|Wv] (64x16)
        int kk = tid >> 6, l = tid & 31;
        int c = l & 3, g = l >> 2;
        int nt = (tid >> 5) & 1;
        int col = nt * 8 + g;  // 0..15: first 8 = k, last 8 = v
        const float* W = (col < 8) ? Wk : Wv;
        int cc = col & 7;
        int k0 = kk * 16 + 2 * c;
        uint32_t h0, l0, h1, l1;
        split2(W[k0 * 8 + cc],       W[(k0 + 1) * 8 + cc], h0, l0);
        split2(W[(k0 + 8) * 8 + cc], W[(k0 + 9) * 8 + cc], h1, l1);
        g_wKV[tid] = make_uint4(h0, h1, l0, l1);
    }
}

// ---------------- shared body: load m chunk, LN, split into bf16 planes ----
// plane[0..128*PSTR)       : hi plane (row stride PSTR words, k-pairs packed)
// plane[128*PSTR..2*)      : lo plane
// the same buffer doubles as the fp32 staging area (stride 68 floats)
__device__ __forceinline__ void load_ln_split(const float* __restrict__ mb,
                                              const float* __restrict__ lw,
                                              const float* __restrict__ lb,
                                              uint32_t* plane, int tid) {
    float* stage = reinterpret_cast<float*>(plane);
#pragma unroll
    for (int i = 0; i < 8; i++) {
        int f = tid + i * 256, row = f >> 4, q = f & 15;
        *reinterpret_cast<float4*>(stage + row * 68 + q * 4) =
            *reinterpret_cast<const float4*>(mb + (size_t)row * (RL * 64) + q * 4);
    }
    __syncthreads();
    float v[64];
    bool act = tid < 128;
    if (act) {
#pragma unroll
        for (int q = 0; q < 16; q++) {
            float4 t = *reinterpret_cast<float4*>(stage + tid * 68 + q * 4);
            v[4 * q] = t.x; v[4 * q + 1] = t.y; v[4 * q + 2] = t.z; v[4 * q + 3] = t.w;
        }
        float s = 0.f;
#pragma unroll
        for (int c = 0; c < 64; c++) s += v[c];
        float mu = s * (1.f / 64.f);
        float s2 = 0.f;
#pragma unroll
        for (int c = 0; c < 64; c++) { float d = v[c] - mu; s2 += d * d; }
        float inv = rsqrtf(s2 * (1.f / 64.f) + 1e-5f);
#pragma unroll
        for (int c = 0; c < 64; c++) v[c] = (v[c] - mu) * inv * lw[c] + lb[c];
    }
    __syncthreads();   // all stage reads done before plane writes clobber it
    if (act) {
        uint32_t* hip = plane + tid * PSTR;
        uint32_t* lop = plane + 128 * PSTR + tid * PSTR;
#pragma unroll
        for (int q = 0; q < 32; q++) {
            uint32_t h, lo;
            split2(v[2 * q], v[2 * q + 1], h, lo);
            hip[q] = h; lop[q] = lo;
        }
    }
    __syncthreads();
}

// ---------------- pass A: LN + pool partial + k,v GEMM ---------------------
__global__ __launch_bounds__(256, 3) void passA(const float* __restrict__ m,
                                                const float* __restrict__ lnw,
                                                const float* __restrict__ lnb) {
    __shared__ __align__(16) uint32_t plane[2 * 128 * PSTR];
    __shared__ float lw[64], lb[64];
    int chunk = blockIdx.x, r = blockIdx.y, tid = threadIdx.x;
    if (tid < 64) { lw[tid] = lnw[tid]; lb[tid] = lnb[tid]; }
    const float* mb = m + ((size_t)chunk * 128 * RL + r) * 64;
    load_ln_split(mb, lw, lb, plane, tid);

    // deterministic partial pool (reconstruct x = hi + lo)
    if (tid < 64) {
        int q = tid >> 1, sh = (tid & 1) * 16;
        float s = 0.f;
#pragma unroll 4
        for (int j = 0; j < 128; j++)
            s += bfhalf(plane[j * PSTR + q], sh) + bfhalf(plane[128 * PSTR + j * PSTR + q], sh);
        g_pool[((size_t)chunk * RL + r) * 64 + tid] = s;
    }

    // k,v GEMM: 128x16x64, bf16x3 m16n8k16
    int w = tid >> 5, l = tid & 31, g = l >> 2, c = l & 3;
    int row0 = w * 16 + g;
    const uint32_t* hip = plane;
    const uint32_t* lop = plane + 128 * PSTR;
    float acc[2][4] = {};
#pragma unroll
    for (int kk = 0; kk < 4; kk++) {
        uint32_t ah[4], al[4];
        int b0 = row0 * PSTR + 8 * kk + c, b1 = (row0 + 8) * PSTR + 8 * kk + c;
        ah[0] = hip[b0]; ah[1] = hip[b1]; ah[2] = hip[b0 + 4]; ah[3] = hip[b1 + 4];
        al[0] = lop[b0]; al[1] = lop[b1]; al[2] = lop[b0 + 4]; al[3] = lop[b1 + 4];
#pragma unroll
        for (int nn = 0; nn < 2; nn++) {
            uint4 bw = g_wKV[(kk * 2 + nn) * 32 + l];
            uint32_t bh[2] = {bw.x, bw.y}, bl[2] = {bw.z, bw.w};
            mma16(acc[nn], ah, bh);
            mma16(acc[nn], al, bh);
            mma16(acc[nn], ah, bl);
        }
    }
    float* kp = g_kv + ((size_t)r * SL + (size_t)chunk * 128 + w * 16) * 16;
#pragma unroll
    for (int nn = 0; nn < 2; nn++) {
        int col = nn * 8 + 2 * c;
        *reinterpret_cast<float2*>(&kp[g * 16 + col])       = make_float2(acc[nn][0], acc[nn][1]);
        *reinterpret_cast<float2*>(&kp[(g + 8) * 16 + col]) = make_float2(acc[nn][2], acc[nn][3]);
    }
}

// ---------------- pass B: q, softmax over s, o -----------------------------
__global__ __launch_bounds__(256) void passB(const float* __restrict__ Wq) {
    int r = blockIdx.x, tid = threadIdx.x;
    __shared__ float pool[64], qs[64], mh[8];
    __shared__ float red[8 * 72];
    if (tid < 64) {
        float s = 0.f;
#pragma unroll
        for (int ch = 0; ch < NCH; ch++) s += g_pool[((size_t)ch * RL + r) * 64 + tid];
        pool[tid] = s / (2048.f + 1e-10f);
    }
    __syncthreads();
    if (tid < 64) {
        float a = 0.f;
        for (int c = 0; c < 64; c++) a += pool[c] * Wq[c * 64 + tid];
        qs[tid] = a * 0.35355339059327373f;  // 8^-0.5
    }
    __syncthreads();

    const float* kvr = g_kv + (size_t)r * SL * 16;
    float lmx[8];
#pragma unroll
    for (int h = 0; h < 8; h++) lmx[h] = -1e30f;
    for (int i = 0; i < 8; i++) {
        int s = tid + i * 256;
        float4 k0 = *reinterpret_cast<const float4*>(kvr + (size_t)s * 16);
        float4 k1 = *reinterpret_cast<const float4*>(kvr + (size_t)s * 16 + 4);
#pragma unroll
        for (int h = 0; h < 8; h++) {
            const float* q = &qs[h * 8];
            float lg = q[0] * k0.x + q[1] * k0.y + q[2] * k0.z + q[3] * k0.w +
                       q[4] * k1.x + q[5] * k1.y + q[6] * k1.z + q[7] * k1.w;
            lmx[h] = fmaxf(lmx[h], lg);
        }
    }
#pragma unroll
    for (int o = 16; o; o >>= 1)
#pragma unroll
        for (int h = 0; h < 8; h++) lmx[h] = fmaxf(lmx[h], __shfl_xor_sync(~0u, lmx[h], o));
    int w = tid >> 5, ln = tid & 31;
    if (ln == 0)
        for (int h = 0; h < 8; h++) red[w * 8 + h] = lmx[h];
    __syncthreads();
    if (tid < 8) {
        float mm = -1e30f;
        for (int ww = 0; ww < 8; ww++) mm = fmaxf(mm, red[ww * 8 + tid]);
        mh[tid] = mm;
    }
    __syncthreads();

    float acc[64], sums[8];
#pragma unroll
    for (int j = 0; j < 64; j++) acc[j] = 0.f;
#pragma unroll
    for (int h = 0; h < 8; h++) sums[h] = 0.f;
    for (int i = 0; i < 8; i++) {
        int s = tid + i * 256;
        float4 k0 = *reinterpret_cast<const float4*>(kvr + (size_t)s * 16);
        float4 k1 = *reinterpret_cast<const float4*>(kvr + (size_t)s * 16 + 4);
        float4 v0 = *reinterpret_cast<const float4*>(kvr + (size_t)s * 16 + 8);
        float4 v1 = *reinterpret_cast<const float4*>(kvr + (size_t)s * 16 + 12);
        float vv[8] = {v0.x, v0.y, v0.z, v0.w, v1.x, v1.y, v1.z, v1.w};
#pragma unroll
        for (int h = 0; h < 8; h++) {
            const float* q = &qs[h * 8];
            float lg = q[0] * k0.x + q[1] * k0.y + q[2] * k0.z + q[3] * k0.w +
                       q[4] * k1.x + q[5] * k1.y + q[6] * k1.z + q[7] * k1.w;
            float p = __expf(lg - mh[h]);
            sums[h] += p;
#pragma unroll
            for (int c2 = 0; c2 < 8; c2++) acc[h * 8 + c2] += p * vv[c2];
        }
    }
#pragma unroll
    for (int o = 16; o; o >>= 1) {
#pragma unroll
        for (int h = 0; h < 8; h++) sums[h] += __shfl_xor_sync(~0u, sums[h], o);
#pragma unroll
        for (int j = 0; j < 64; j++) acc[j] += __shfl_xor_sync(~0u, acc[j], o);
    }
    __syncthreads();
    if (ln == 0) {
        for (int h = 0; h < 8; h++) red[w * 72 + h] = sums[h];
        for (int j = 0; j < 64; j++) red[w * 72 + 8 + j] = acc[j];
    }
    __syncthreads();
    if (tid < 64) {
        float a = 0.f, ss = 0.f;
        for (int ww = 0; ww < 8; ww++) a += red[ww * 72 + 8 + tid];
        for (int ww = 0; ww < 8; ww++) ss += red[ww * 72 + (tid >> 3)];
        g_obuf[r * 64 + tid] = a / ss;
    }
}

// ---------------- pass C: LN + GEMM1(sig*o) + GEMM2 + store ----------------
__global__ __launch_bounds__(256, 3) void passC(const float* __restrict__ m,
                                                const float* __restrict__ lnw,
                                                const float* __restrict__ lnb,
                                                const float* __restrict__ bg,
                                                const float* __restrict__ bo,
                                                float* __restrict__ out) {
    __shared__ __align__(16) uint32_t plane[2 * 128 * PSTR];
    __shared__ float lw[64], lb[64], sg[64], sb[64], so[64];
    int chunk = blockIdx.x, r = blockIdx.y, tid = threadIdx.x;
    if (tid < 64) {
        lw[tid] = lnw[tid]; lb[tid] = lnb[tid];
        sg[tid] = bg[tid];  sb[tid] = bo[tid];
        so[tid] = g_obuf[r * 64 + tid];
    }
    const float* mb = m + ((size_t)chunk * 128 * RL + r) * 64;
    load_ln_split(mb, lw, lb, plane, tid);

    int w = tid >> 5, l = tid & 31, g = l >> 2, c = l & 3;
    int row0 = w * 16 + g;
    uint32_t* hip = plane;
    uint32_t* lop = plane + 128 * PSTR;

    // GEMM1: x(128x64) @ Wg(64x64), bf16x3
    float acc[8][4] = {};
#pragma unroll
    for (int kk = 0; kk < 4; kk++) {
        uint32_t ah[4], al[4];
        int b0 = row0 * PSTR + 8 * kk + c, b1 = (row0 + 8) * PSTR + 8 * kk + c;
        ah[0] = hip[b0]; ah[1] = hip[b1]; ah[2] = hip[b0 + 4]; ah[3] = hip[b1 + 4];
        al[0] = lop[b0]; al[1] = lop[b1]; al[2] = lop[b0 + 4]; al[3] = lop[b1 + 4];
#pragma unroll
        for (int nn = 0; nn < 8; nn++) {
            uint4 bw = g_wG[(kk * 8 + nn) * 32 + l];
            uint32_t bh[2] = {bw.x, bw.y}, bl[2] = {bw.z, bw.w};
            mma16(acc[nn], ah, bh);
            mma16(acc[nn], al, bh);
            mma16(acc[nn], ah, bl);
        }
    }
    __syncwarp();  // each warp only touches its own 16 rows; cross-lane within warp

    // epilogue: z = sigmoid(acc + bg) * o  -> split back into planes
#pragma unroll
    for (int nn = 0; nn < 8; nn++) {
        int col = nn * 8 + 2 * c;
        float z0 = sigm(acc[nn][0] + sg[col])     * so[col];
        float z1 = sigm(acc[nn][1] + sg[col + 1]) * so[col + 1];
        float z2 = sigm(acc[nn][2] + sg[col])     * so[col];
        float z3 = sigm(acc[nn][3] + sg[col + 1]) * so[col + 1];
        uint32_t h, lo;
        split2(z0, z1, h, lo);
        hip[row0 * PSTR + 4 * nn + c] = h; lop[row0 * PSTR + 4 * nn + c] = lo;
        split2(z2, z3, h, lo);
        hip[(row0 + 8) * PSTR + 4 * nn + c] = h; lop[(row0 + 8) * PSTR + 4 * nn + c] = lo;
        acc[nn][0] = acc[nn][1] = acc[nn][2] = acc[nn][3] = 0.f;
    }
    __syncwarp();

    // GEMM2: z(128x64) @ Wo(64x64), bf16x3
#pragma unroll
    for (int kk = 0; kk < 4; kk++) {
        uint32_t ah[4], al[4];
        int b0 = row0 * PSTR + 8 * kk + c, b1 = (row0 + 8) * PSTR + 8 * kk + c;
        ah[0] = hip[b0]; ah[1] = hip[b1]; ah[2] = hip[b0 + 4]; ah[3] = hip[b1 + 4];
        al[0] = lop[b0]; al[1] = lop[b1]; al[2] = lop[b0 + 4]; al[3] = lop[b1 + 4];
#pragma unroll
        for (int nn = 0; nn < 8; nn++) {
            uint4 bw = g_wO[(kk * 8 + nn) * 32 + l];
            uint32_t bh[2] = {bw.x, bw.y}, bl[2] = {bw.z, bw.w};
            mma16(acc[nn], ah, bh);
            mma16(acc[nn], al, bh);
            mma16(acc[nn], ah, bl);
        }
    }

    // store: out[s][r][c] with bias bo
    float* ob = out + ((size_t)chunk * 128 * RL + r) * 64;
#pragma unroll
    for (int nn = 0; nn < 8; nn++) {
        int col = nn * 8 + 2 * c;
        *reinterpret_cast<float2*>(&ob[(size_t)row0 * (RL * 64) + col]) =
            make_float2(acc[nn][0] + sb[col], acc[nn][1] + sb[col + 1]);
        *reinterpret_cast<float2*>(&ob[(size_t)(row0 + 8) * (RL * 64) + col]) =
            make_float2(acc[nn][2] + sb[col], acc[nn][3] + sb[col + 1]);
    }
}

// ---------------- launch ----------------------------------------------------
extern "C" void kernel_launch(void* const* d_in, const int* in_sizes, int n_in,
                              void* d_out, int out_size) {
    const float* m   = (const float*)d_in[0];
    const float* lnw = (const float*)d_in[1];
    const float* lnb = (const float*)d_in[2];
    const float* Wq  = (const float*)d_in[3];
    const float* Wk  = (const float*)d_in[4];
    const float* Wv  = (const float*)d_in[5];
    const float* Wg  = (const float*)d_in[6];
    const float* bg  = (const float*)d_in[7];
    const float* Wo  = (const float*)d_in[8];
    const float* bo  = (const float*)d_in[9];
    float* out = (float*)d_out;

    init_kernel<<<4, 256>>>(Wg, Wo, Wk, Wv);
    dim3 gA(NCH, RL);
    passA<<<gA, 256>>>(m, lnw, lnb);
    passB<<<RL, 256>>>(Wq);
    passC<<<gA, 256>>>(m, lnw, lnb, bg, bo, out);
}

// round 9
// speedup vs baseline: 1.0100x; 1.0010x over previous
#include <cuda_runtime.h>
#include <cuda_bf16.h>
#include <cstdint>

#define SL 2048
#define RL 384
#define NCH 16     // s-chunks of 128
#define PSTR 36    // plane row stride in 32-bit words (conflict-free: bank=(4g+c)&31)

// ---------------- device scratch (no runtime allocation allowed) ----------
__device__ __align__(16) float  g_kv[(size_t)RL * SL * 16];   // k|v per (r,s): 50MB
__device__ __align__(16) float  g_pool[NCH * RL * 64];        // partial pools
__device__ __align__(16) float  g_obuf[RL * 64];              // attention output per column
__device__ __align__(16) uint4  g_wG[4 * 8 * 32];             // Wg bf16 frags {bh0,bh1,bl0,bl1}
__device__ __align__(16) uint4  g_wO[4 * 8 * 32];             // Wo frags
__device__ __align__(16) uint4  g_wKV[4 * 2 * 32];            // [Wk|Wv] frags

// ---------------- helpers --------------------------------------------------
__device__ __forceinline__ uint32_t pack2(__nv_bfloat16 a, __nv_bfloat16 b) {
    __nv_bfloat162 t; t.x = a; t.y = b;
    return *reinterpret_cast<uint32_t*>(&t);
}
// split two floats into packed bf16 hi-word and lo-word (x = hi + lo, err ~2^-17)
__device__ __forceinline__ void split2(float x0, float x1, uint32_t& hi, uint32_t& lo) {
    __nv_bfloat16 h0 = __float2bfloat16(x0), h1 = __float2bfloat16(x1);
    float r0 = x0 - __bfloat162float(h0), r1 = x1 - __bfloat162float(h1);
    hi = pack2(h0, h1);
    lo = pack2(__float2bfloat16(r0), __float2bfloat16(r1));
}
__device__ __forceinline__ float bfhalf(uint32_t w, int sh) {
    return __bfloat162float(__ushort_as_bfloat16((unsigned short)(w >> sh)));
}
__device__ __forceinline__ void mma16(float* d, const uint32_t* a, const uint32_t* b) {
    asm volatile(
        "mma.sync.aligned.m16n8k16.row.col.f32.bf16.bf16.f32 "
        "{%0,%1,%2,%3}, {%4,%5,%6,%7}, {%8,%9}, {%0,%1,%2,%3};"
        : "+f"(d[0]), "+f"(d[1]), "+f"(d[2]), "+f"(d[3])
        : "r"(a[0]), "r"(a[1]), "r"(a[2]), "r"(a[3]), "r"(b[0]), "r"(b[1]));
}
__device__ __forceinline__ float sigm(float x) { return 1.f / (1.f + __expf(-x)); }

// ---------------- init: build bf16 hi/lo B fragments (m16n8k16 col-major) --
__global__ void init_kernel(const float* __restrict__ Wg, const float* __restrict__ Wo,
                            const float* __restrict__ Wk, const float* __restrict__ Wv) {
    int tid = blockIdx.x * blockDim.x + threadIdx.x;
    if (tid < 1024) {  // 4 ktiles(k16) x 8 ntiles x 32 lanes for Wg/Wo (64x64)
        int kk = tid >> 8, l = tid & 31;
        int c = l & 3, g = l >> 2;
        int nn = (tid >> 5) & 7;
        int col = nn * 8 + g;
        int k0 = kk * 16 + 2 * c;
        {
            uint32_t h0, l0, h1, l1;
            split2(Wg[k0 * 64 + col],       Wg[(k0 + 1) * 64 + col], h0, l0);
            split2(Wg[(k0 + 8) * 64 + col], Wg[(k0 + 9) * 64 + col], h1, l1);
            g_wG[tid] = make_uint4(h0, h1, l0, l1);
        }
        {
            uint32_t h0, l0, h1, l1;
            split2(Wo[k0 * 64 + col],       Wo[(k0 + 1) * 64 + col], h0, l0);
            split2(Wo[(k0 + 8) * 64 + col], Wo[(k0 + 9) * 64 + col], h1, l1);
            g_wO[tid] = make_uint4(h0, h1, l0, l1);
        }
    }
    if (tid < 256) {  // 4 ktiles x 2 ntiles x 32 lanes for [Wk|Wv] (64x16)
        int kk = tid >> 6, l = tid & 31;
        int c = l & 3, g = l >> 2;
        int nt = (tid >> 5) & 1;
        int col = nt * 8 + g;  // 0..15: first 8 = k, last 8 = v
        const float* W = (col < 8) ? Wk : Wv;
        int cc = col & 7;
        int k0 = kk * 16 + 2 * c;
        uint32_t h0, l0, h1, l1;
        split2(W[k0 * 8 + cc],       W[(k0 + 1) * 8 + cc], h0, l0);
        split2(W[(k0 + 8) * 8 + cc], W[(k0 + 9) * 8 + cc], h1, l1);
        g_wKV[tid] = make_uint4(h0, h1, l0, l1);
    }
}

// ---------------- shared body: load m chunk, LN, split into bf16 planes ----
// plane[0..128*PSTR)       : hi plane (row stride PSTR words, k-pairs packed)
// plane[128*PSTR..2*)      : lo plane
// the same buffer doubles as the fp32 staging area (stride 68 floats)
__device__ __forceinline__ void load_ln_split(const float* __restrict__ mb,
                                              const float* __restrict__ lw,
                                              const float* __restrict__ lb,
                                              uint32_t* plane, int tid) {
    float* stage = reinterpret_cast<float*>(plane);
#pragma unroll
    for (int i = 0; i < 8; i++) {
        int f = tid + i * 256, row = f >> 4, q = f & 15;
        *reinterpret_cast<float4*>(stage + row * 68 + q * 4) =
            *reinterpret_cast<const float4*>(mb + (size_t)row * (RL * 64) + q * 4);
    }
    __syncthreads();
    float v[64];
    bool act = tid < 128;
    if (act) {
#pragma unroll
        for (int q = 0; q < 16; q++) {
            float4 t = *reinterpret_cast<float4*>(stage + tid * 68 + q * 4);
            v[4 * q] = t.x; v[4 * q + 1] = t.y; v[4 * q + 2] = t.z; v[4 * q + 3] = t.w;
        }
        float s = 0.f;
#pragma unroll
        for (int c = 0; c < 64; c++) s += v[c];
        float mu = s * (1.f / 64.f);
        float s2 = 0.f;
#pragma unroll
        for (int c = 0; c < 64; c++) { float d = v[c] - mu; s2 += d * d; }
        float inv = rsqrtf(s2 * (1.f / 64.f) + 1e-5f);
#pragma unroll
        for (int c = 0; c < 64; c++) v[c] = (v[c] - mu) * inv * lw[c] + lb[c];
    }
    __syncthreads();   // all stage reads done before plane writes clobber it
    if (act) {
        uint32_t* hip = plane + tid * PSTR;
        uint32_t* lop = plane + 128 * PSTR + tid * PSTR;
#pragma unroll
        for (int q = 0; q < 32; q++) {
            uint32_t h, lo;
            split2(v[2 * q], v[2 * q + 1], h, lo);
            hip[q] = h; lop[q] = lo;
        }
    }
    __syncthreads();
}

// ---------------- pass A: LN + pool partial + k,v GEMM ---------------------
__global__ __launch_bounds__(256, 3) void passA(const float* __restrict__ m,
                                                const float* __restrict__ lnw,
                                                const float* __restrict__ lnb) {
    __shared__ __align__(16) uint32_t plane[2 * 128 * PSTR];
    __shared__ float lw[64], lb[64];
    int chunk = blockIdx.x, r = blockIdx.y, tid = threadIdx.x;
    if (tid < 64) { lw[tid] = lnw[tid]; lb[tid] = lnb[tid]; }
    const float* mb = m + ((size_t)chunk * 128 * RL + r) * 64;
    load_ln_split(mb, lw, lb, plane, tid);

    // deterministic partial pool (reconstruct x = hi + lo)
    if (tid < 64) {
        int q = tid >> 1, sh = (tid & 1) * 16;
        float s = 0.f;
#pragma unroll 4
        for (int j = 0; j < 128; j++)
            s += bfhalf(plane[j * PSTR + q], sh) + bfhalf(plane[128 * PSTR + j * PSTR + q], sh);
        g_pool[((size_t)chunk * RL + r) * 64 + tid] = s;
    }

    // k,v GEMM: 128x16x64, bf16x3 m16n8k16
    int w = tid >> 5, l = tid & 31, g = l >> 2, c = l & 3;
    int row0 = w * 16 + g;
    const uint32_t* hip = plane;
    const uint32_t* lop = plane + 128 * PSTR;
    float acc[2][4] = {};
#pragma unroll
    for (int kk = 0; kk < 4; kk++) {
        uint32_t ah[4], al[4];
        int b0 = row0 * PSTR + 8 * kk + c, b1 = (row0 + 8) * PSTR + 8 * kk + c;
        ah[0] = hip[b0]; ah[1] = hip[b1]; ah[2] = hip[b0 + 4]; ah[3] = hip[b1 + 4];
        al[0] = lop[b0]; al[1] = lop[b1]; al[2] = lop[b0 + 4]; al[3] = lop[b1 + 4];
#pragma unroll
        for (int nn = 0; nn < 2; nn++) {
            uint4 bw = g_wKV[(kk * 2 + nn) * 32 + l];
            uint32_t bh[2] = {bw.x, bw.y}, bl[2] = {bw.z, bw.w};
            mma16(acc[nn], ah, bh);
            mma16(acc[nn], al, bh);
            mma16(acc[nn], ah, bl);
        }
    }
    float* kp = g_kv + ((size_t)r * SL + (size_t)chunk * 128 + w * 16) * 16;
#pragma unroll
    for (int nn = 0; nn < 2; nn++) {
        int col = nn * 8 + 2 * c;
        *reinterpret_cast<float2*>(&kp[g * 16 + col])       = make_float2(acc[nn][0], acc[nn][1]);
        *reinterpret_cast<float2*>(&kp[(g + 8) * 16 + col]) = make_float2(acc[nn][2], acc[nn][3]);
    }
}

// ---------------- pass B: q, softmax over s, o -----------------------------
__global__ __launch_bounds__(256) void passB(const float* __restrict__ Wq) {
    int r = blockIdx.x, tid = threadIdx.x;
    __shared__ float pool[64], qs[64], mh[8];
    __shared__ float red[8 * 72];
    if (tid < 64) {
        float s = 0.f;
#pragma unroll
        for (int ch = 0; ch < NCH; ch++) s += g_pool[((size_t)ch * RL + r) * 64 + tid];
        pool[tid] = s / (2048.f + 1e-10f);
    }
    __syncthreads();
    if (tid < 64) {
        float a = 0.f;
        for (int c = 0; c < 64; c++) a += pool[c] * Wq[c * 64 + tid];
        qs[tid] = a * 0.35355339059327373f;  // 8^-0.5
    }
    __syncthreads();

    const float* kvr = g_kv + (size_t)r * SL * 16;
    float lmx[8];
#pragma unroll
    for (int h = 0; h < 8; h++) lmx[h] = -1e30f;
    for (int i = 0; i < 8; i++) {
        int s = tid + i * 256;
        float4 k0 = *reinterpret_cast<const float4*>(kvr + (size_t)s * 16);
        float4 k1 = *reinterpret_cast<const float4*>(kvr + (size_t)s * 16 + 4);
#pragma unroll
        for (int h = 0; h < 8; h++) {
            const float* q = &qs[h * 8];
            float lg = q[0] * k0.x + q[1] * k0.y + q[2] * k0.z + q[3] * k0.w +
                       q[4] * k1.x + q[5] * k1.y + q[6] * k1.z + q[7] * k1.w;
            lmx[h] = fmaxf(lmx[h], lg);
        }
    }
#pragma unroll
    for (int o = 16; o; o >>= 1)
#pragma unroll
        for (int h = 0; h < 8; h++) lmx[h] = fmaxf(lmx[h], __shfl_xor_sync(~0u, lmx[h], o));
    int w = tid >> 5, ln = tid & 31;
    if (ln == 0)
        for (int h = 0; h < 8; h++) red[w * 8 + h] = lmx[h];
    __syncthreads();
    if (tid < 8) {
        float mm = -1e30f;
        for (int ww = 0; ww < 8; ww++) mm = fmaxf(mm, red[ww * 8 + tid]);
        mh[tid] = mm;
    }
    __syncthreads();

    float acc[64], sums[8];
#pragma unroll
    for (int j = 0; j < 64; j++) acc[j] = 0.f;
#pragma unroll
    for (int h = 0; h < 8; h++) sums[h] = 0.f;
    for (int i = 0; i < 8; i++) {
        int s = tid + i * 256;
        float4 k0 = *reinterpret_cast<const float4*>(kvr + (size_t)s * 16);
        float4 k1 = *reinterpret_cast<const float4*>(kvr + (size_t)s * 16 + 4);
        float4 v0 = *reinterpret_cast<const float4*>(kvr + (size_t)s * 16 + 8);
        float4 v1 = *reinterpret_cast<const float4*>(kvr + (size_t)s * 16 + 12);
        float vv[8] = {v0.x, v0.y, v0.z, v0.w, v1.x, v1.y, v1.z, v1.w};
#pragma unroll
        for (int h = 0; h < 8; h++) {
            const float* q = &qs[h * 8];
            float lg = q[0] * k0.x + q[1] * k0.y + q[2] * k0.z + q[3] * k0.w +
                       q[4] * k1.x + q[5] * k1.y + q[6] * k1.z + q[7] * k1.w;
            float p = __expf(lg - mh[h]);
            sums[h] += p;
#pragma unroll
            for (int c2 = 0; c2 < 8; c2++) acc[h * 8 + c2] += p * vv[c2];
        }
    }
#pragma unroll
    for (int o = 16; o; o >>= 1) {
#pragma unroll
        for (int h = 0; h < 8; h++) sums[h] += __shfl_xor_sync(~0u, sums[h], o);
#pragma unroll
        for (int j = 0; j < 64; j++) acc[j] += __shfl_xor_sync(~0u, acc[j], o);
    }
    __syncthreads();
    if (ln == 0) {
        for (int h = 0; h < 8; h++) red[w * 72 + h] = sums[h];
        for (int j = 0; j < 64; j++) red[w * 72 + 8 + j] = acc[j];
    }
    __syncthreads();
    if (tid < 64) {
        float a = 0.f, ss = 0.f;
        for (int ww = 0; ww < 8; ww++) a += red[ww * 72 + 8 + tid];
        for (int ww = 0; ww < 8; ww++) ss += red[ww * 72 + (tid >> 3)];
        g_obuf[r * 64 + tid] = a / ss;
    }
}

// ---------------- pass C: LN + GEMM1(sig*o) + GEMM2 + store ----------------
__global__ __launch_bounds__(256, 3) void passC(const float* __restrict__ m,
                                                const float* __restrict__ lnw,
                                                const float* __restrict__ lnb,
                                                const float* __restrict__ bg,
                                                const float* __restrict__ bo,
                                                float* __restrict__ out) {
    __shared__ __align__(16) uint32_t plane[2 * 128 * PSTR];
    __shared__ float lw[64], lb[64], sg[64], sb[64], so[64];
    int chunk = blockIdx.x, r = blockIdx.y, tid = threadIdx.x;
    if (tid < 64) {
        lw[tid] = lnw[tid]; lb[tid] = lnb[tid];
        sg[tid] = bg[tid];  sb[tid] = bo[tid];
        so[tid] = g_obuf[r * 64 + tid];
    }
    const float* mb = m + ((size_t)chunk * 128 * RL + r) * 64;
    load_ln_split(mb, lw, lb, plane, tid);

    int w = tid >> 5, l = tid & 31, g = l >> 2, c = l & 3;
    int row0 = w * 16 + g;
    uint32_t* hip = plane;
    uint32_t* lop = plane + 128 * PSTR;

    // GEMM1: x(128x64) @ Wg(64x64), bf16x3
    float acc[8][4] = {};
#pragma unroll
    for (int kk = 0; kk < 4; kk++) {
        uint32_t ah[4], al[4];
        int b0 = row0 * PSTR + 8 * kk + c, b1 = (row0 + 8) * PSTR + 8 * kk + c;
        ah[0] = hip[b0]; ah[1] = hip[b1]; ah[2] = hip[b0 + 4]; ah[3] = hip[b1 + 4];
        al[0] = lop[b0]; al[1] = lop[b1]; al[2] = lop[b0 + 4]; al[3] = lop[b1 + 4];
#pragma unroll
        for (int nn = 0; nn < 8; nn++) {
            uint4 bw = g_wG[(kk * 8 + nn) * 32 + l];
            uint32_t bh[2] = {bw.x, bw.y}, bl[2] = {bw.z, bw.w};
            mma16(acc[nn], ah, bh);
            mma16(acc[nn], al, bh);
            mma16(acc[nn], ah, bl);
        }
    }
    __syncwarp();  // each warp only touches its own 16 rows; cross-lane within warp

    // epilogue: z = sigmoid(acc + bg) * o  -> split back into planes
#pragma unroll
    for (int nn = 0; nn < 8; nn++) {
        int col = nn * 8 + 2 * c;
        float z0 = sigm(acc[nn][0] + sg[col])     * so[col];
        float z1 = sigm(acc[nn][1] + sg[col + 1]) * so[col + 1];
        float z2 = sigm(acc[nn][2] + sg[col])     * so[col];
        float z3 = sigm(acc[nn][3] + sg[col + 1]) * so[col + 1];
        uint32_t h, lo;
        split2(z0, z1, h, lo);
        hip[row0 * PSTR + 4 * nn + c] = h; lop[row0 * PSTR + 4 * nn + c] = lo;
        split2(z2, z3, h, lo);
        hip[(row0 + 8) * PSTR + 4 * nn + c] = h; lop[(row0 + 8) * PSTR + 4 * nn + c] = lo;
        acc[nn][0] = acc[nn][1] = acc[nn][2] = acc[nn][3] = 0.f;
    }
    __syncwarp();

    // GEMM2: z(128x64) @ Wo(64x64), bf16x3
#pragma unroll
    for (int kk = 0; kk < 4; kk++) {
        uint32_t ah[4], al[4];
        int b0 = row0 * PSTR + 8 * kk + c, b1 = (row0 + 8) * PSTR + 8 * kk + c;
        ah[0] = hip[b0]; ah[1] = hip[b1]; ah[2] = hip[b0 + 4]; ah[3] = hip[b1 + 4];
        al[0] = lop[b0]; al[1] = lop[b1]; al[2] = lop[b0 + 4]; al[3] = lop[b1 + 4];
#pragma unroll
        for (int nn = 0; nn < 8; nn++) {
            uint4 bw = g_wO[(kk * 8 + nn) * 32 + l];
            uint32_t bh[2] = {bw.x, bw.y}, bl[2] = {bw.z, bw.w};
            mma16(acc[nn], ah, bh);
            mma16(acc[nn], al, bh);
            mma16(acc[nn], ah, bl);
        }
    }

    // store: out[s][r][c] with bias bo
    float* ob = out + ((size_t)chunk * 128 * RL + r) * 64;
#pragma unroll
    for (int nn = 0; nn < 8; nn++) {
        int col = nn * 8 + 2 * c;
        *reinterpret_cast<float2*>(&ob[(size_t)row0 * (RL * 64) + col]) =
            make_float2(acc[nn][0] + sb[col], acc[nn][1] + sb[col + 1]);
        *reinterpret_cast<float2*>(&ob[(size_t)(row0 + 8) * (RL * 64) + col]) =
            make_float2(acc[nn][2] + sb[col], acc[nn][3] + sb[col + 1]);
    }
}

// ---------------- launch ----------------------------------------------------
extern "C" void kernel_launch(void* const* d_in, const int* in_sizes, int n_in,
                              void* d_out, int out_size) {
    const float* m   = (const float*)d_in[0];
    const float* lnw = (const float*)d_in[1];
    const float* lnb = (const float*)d_in[2];
    const float* Wq  = (const float*)d_in[3];
    const float* Wk  = (const float*)d_in[4];
    const float* Wv  = (const float*)d_in[5];
    const float* Wg  = (const float*)d_in[6];
    const float* bg  = (const float*)d_in[7];
    const float* Wo  = (const float*)d_in[8];
    const float* bo  = (const float*)d_in[9];
    float* out = (float*)d_out;

    init_kernel<<<4, 256>>>(Wg, Wo, Wk, Wv);
    dim3 gA(NCH, RL);
    passA<<<gA, 256>>>(m, lnw, lnb);
    passB<<<RL, 256>>>(Wq);
    passC<<<gA, 256>>>(m, lnw, lnb, bg, bo, out);
}